// round 6
// baseline (speedup 1.0000x reference)
#include <cuda_runtime.h>
#include <cuda_bf16.h>
#include <cstdint>

// Problem constants
constexpr int Bc  = 2;
constexpr int Nc  = 50;
constexpr int NG  = 15;
constexpr int Cc  = 17;
constexpr int HWc = 4096;

constexpr int KCHUNK = 1024;
constexpr int KIN    = 64;
constexpr int NIT    = KCHUNK / KIN;   // 16
constexpr int IPAD   = 64;
constexpr int JPAD   = 16;
constexpr int THREADS = 512;

// one buffer: A,B,C [IPAD][KIN], U,V,W [JPAD][KIN]
constexpr int OFF_A = 0;
constexpr int OFF_B = OFF_A + IPAD * KIN;
constexpr int OFF_C = OFF_B + IPAD * KIN;
constexpr int OFF_U = OFF_C + IPAD * KIN;
constexpr int OFF_V = OFF_U + JPAD * KIN;
constexpr int OFF_W = OFF_V + JPAD * KIN;
constexpr int HALF  = OFF_W + JPAD * KIN;          // 15360 floats
constexpr size_t SMEM_BYTES = 2 * HALF * sizeof(float);  // 120 KB

__device__ float g_acc[Bc * Nc * NG];
__device__ float g_sa[Bc * Nc * Cc];
__device__ int   g_mask[Bc * NG * Cc];

#define FMA_F32X2(d, a, b, c) \
    asm("fma.rn.f32x2 %0, %1, %2, %3;" : "=l"(d) : "l"(a), "l"(b), "l"(c))

// ---------------------------------------------------------------------------
// Kernel 1: zero g_acc/g_sa + channel mask, warp-per-channel early-exit
// grid 32, block 512  (510 channels -> 510 warps of 512 total)
// ---------------------------------------------------------------------------
__global__ void mask_kernel(const float* __restrict__ gh) {
    int tid  = threadIdx.x;
    int gtid = blockIdx.x * THREADS + tid;

    for (int z = gtid; z < Bc * Nc * NG; z += 32 * THREADS) g_acc[z] = 0.0f;
    for (int z = gtid; z < Bc * Nc * Cc; z += 32 * THREADS) g_sa[z]  = 0.0f;

    int wch  = gtid >> 5;                // channel id 0..511
    int lane = tid & 31;
    if (wch < Bc * NG * Cc) {
        const float4* b4 =
            reinterpret_cast<const float4*>(gh + (size_t)wch * HWc);
        int found = 0;
        for (int k = lane; k < HWc / 4; k += 32) {
            float4 v = b4[k];
            int has = (v.x > 0.f) | (v.y > 0.f) | (v.z > 0.f) | (v.w > 0.f);
            found = __any_sync(0xffffffffu, has);
            if (found) break;            // uniform
        }
        if (lane == 0) g_mask[wch] = found;
    }
}

// ---------------------------------------------------------------------------
// Kernel 2: fused transform + 3-term GEMM, f32x2, double-buffered KIN=64
// grid (4, Cc, Bc) = 136 blocks, block 512 (16 warps)
// warp w: i rows [4w,4w+4); lanes 0-15 -> j 0..7, 16-31 -> j 8..15
// ---------------------------------------------------------------------------
__global__ __launch_bounds__(THREADS, 1)
void gemm_kernel(const float* __restrict__ ph, const float* __restrict__ gh) {
    extern __shared__ float sm[];

    const int b = blockIdx.z, c = blockIdx.y;
    const int k0 = blockIdx.x * KCHUNK;

    const int tid  = threadIdx.x;
    const int lane = tid & 31;
    const int wrp  = tid >> 5;
    const int lk   = lane & 15;
    const int half = lane >> 4;
    const int i_base = wrp * 4;
    const int j_base = half * 8;

    // zero pad rows [Nc, IPAD) in BOTH buffers once
    for (int idx = tid; idx < (IPAD - Nc) * KIN; idx += THREADS) {
#pragma unroll
        for (int bu = 0; bu < 2; bu++) {
            sm[bu * HALF + OFF_A + Nc * KIN + idx] = 0.f;
            sm[bu * HALF + OFF_B + Nc * KIN + idx] = 0.f;
            sm[bu * HALF + OFF_C + Nc * KIN + idx] = 0.f;
        }
    }

    const float* phb = ph + ((size_t)(b * Nc * Cc + c)) * HWc;
    const float* ghb = gh + ((size_t)(b * NG * Cc + c)) * HWc;

    // staging coords: pred item idx = tid + q*512; row=idx>>4, col4=(idx&15)*4
    const int pr0 = tid >> 4;            // q=0 row (0..31)
    const int pc0 = (tid & 15) << 2;
    const int pr1 = (tid + THREADS) >> 4;  // q=1 row (32..63), valid tid<288
    const bool q1v = (tid < (Nc * (KIN / 4) - THREADS));  // tid < 288
    // gt item: tid<256: row=tid>>4 (0..15), col4=(tid&15)*4
    const int gj   = tid >> 4;
    const bool gv  = (tid < JPAD * (KIN / 4));            // tid < 256

    unsigned long long acc[4][8];
#pragma unroll
    for (int ii = 0; ii < 4; ii++)
#pragma unroll
        for (int jj = 0; jj < 8; jj++) acc[ii][jj] = 0ull;

    float saAcc0 = 0.f, saAcc1 = 0.f;    // per-thread sum of A (for g_sa)

    float4 xr0, xr1, gr;

    // helper: transform current regs into buffer bw; returns myW
    auto do_transform = [&](float* bw, float4 x0, float4 x1, float4 g) -> int {
        int myW = 0;
        // pred q=0
        {
            float4 a4, b4o, c4;
            float* xs = &x0.x; float* as = &a4.x; float* bs = &b4o.x; float* cs = &c4.x;
#pragma unroll
            for (int qq = 0; qq < 4; qq++) {
                float x = xs[qq];
                float e = __expf(-fabsf(x));
                float l = __logf(1.0f + e);
                float r = __fdividef(1.0f, 1.0f + e);
                float p   = (x >= 0.f) ? r : e * r;
                float omp = (x >= 0.f) ? e * r : r;
                float sp   = fmaxf(x, 0.f) + l;
                float spmx = fmaxf(-x, 0.f) + l;
                float p2 = p * p;
                as[qq] = sp * p2;
                bs[qq] = -(x * p2);
                cs[qq] = spmx * omp * omp;
            }
            saAcc0 += a4.x + a4.y + a4.z + a4.w;
            int so = pr0 * KIN + pc0;
            *reinterpret_cast<float4*>(&bw[OFF_A + so]) = a4;
            *reinterpret_cast<float4*>(&bw[OFF_B + so]) = b4o;
            *reinterpret_cast<float4*>(&bw[OFF_C + so]) = c4;
        }
        // pred q=1
        if (q1v) {
            float4 a4, b4o, c4;
            float* xs = &x1.x; float* as = &a4.x; float* bs = &b4o.x; float* cs = &c4.x;
#pragma unroll
            for (int qq = 0; qq < 4; qq++) {
                float x = xs[qq];
                float e = __expf(-fabsf(x));
                float l = __logf(1.0f + e);
                float r = __fdividef(1.0f, 1.0f + e);
                float p   = (x >= 0.f) ? r : e * r;
                float omp = (x >= 0.f) ? e * r : r;
                float sp   = fmaxf(x, 0.f) + l;
                float spmx = fmaxf(-x, 0.f) + l;
                float p2 = p * p;
                as[qq] = sp * p2;
                bs[qq] = -(x * p2);
                cs[qq] = spmx * omp * omp;
            }
            saAcc1 += a4.x + a4.y + a4.z + a4.w;
            int so = pr1 * KIN + pc0;
            *reinterpret_cast<float4*>(&bw[OFF_A + so]) = a4;
            *reinterpret_cast<float4*>(&bw[OFF_B + so]) = b4o;
            *reinterpret_cast<float4*>(&bw[OFF_C + so]) = c4;
        }
        // gt
        if (gv) {
            float4 u4 = {0,0,0,0}, v4 = {0,0,0,0}, w4 = {0,0,0,0};
            if (gj < NG) {
                float* ts = &g.x; float* us = &u4.x; float* vs = &v4.x; float* wsp = &w4.x;
#pragma unroll
                for (int qq = 0; qq < 4; qq++) {
                    float tt = ts[qq];
                    if (tt == 1.0f) { wsp[qq] = 1.0f; myW = 1; }
                    else {
                        float o  = 1.0f - tt;
                        float o2 = o * o;
                        float u  = o2 * o2;
                        us[qq] = u; vs[qq] = tt * u;
                    }
                }
            }
            int so = gj * KIN + pc0;
            *reinterpret_cast<float4*>(&bw[OFF_U + so]) = u4;
            *reinterpret_cast<float4*>(&bw[OFF_V + so]) = v4;
            *reinterpret_cast<float4*>(&bw[OFF_W + so]) = w4;
        }
        return myW;
    };

    auto do_load = [&](int kbase) {
        xr0 = *reinterpret_cast<const float4*>(
            &phb[(size_t)pr0 * Cc * HWc + kbase + pc0]);
        if (q1v)
            xr1 = *reinterpret_cast<const float4*>(
                &phb[(size_t)pr1 * Cc * HWc + kbase + pc0]);
        if (gv && gj < NG)
            gr = *reinterpret_cast<const float4*>(
                &ghb[(size_t)gj * Cc * HWc + kbase + pc0]);
    };

    // ---- prologue: tile 0
    do_load(k0);
    int myW = do_transform(sm, xr0, xr1, gr);
    int hasW = __syncthreads_or(myW);

    for (int t = 0; t < NIT; ++t) {
        float* bufR = sm + (t & 1) * HALF;
        float* bufW = sm + ((t + 1) & 1) * HALF;
        const bool more = (t + 1 < NIT);

        if (more) do_load(k0 + (t + 1) * KIN);   // latency hides under FMA

        // ---- FMA on bufR
#pragma unroll
        for (int s = 0; s < KIN / 32; ++s) {      // 2 s-steps
            const int kk = 2 * lk + 32 * s;
            unsigned long long uj[8], vj[8];
#pragma unroll
            for (int jj = 0; jj < 8; jj++) {
                int jo = (j_base + jj) * KIN + kk;
                uj[jj] = *reinterpret_cast<unsigned long long*>(&bufR[OFF_U + jo]);
                vj[jj] = *reinterpret_cast<unsigned long long*>(&bufR[OFF_V + jo]);
            }
#pragma unroll
            for (int ii = 0; ii < 4; ii++) {
                int io = (i_base + ii) * KIN + kk;
                unsigned long long a2 =
                    *reinterpret_cast<unsigned long long*>(&bufR[OFF_A + io]);
                unsigned long long b2 =
                    *reinterpret_cast<unsigned long long*>(&bufR[OFF_B + io]);
#pragma unroll
                for (int jj = 0; jj < 8; jj++) {
                    FMA_F32X2(acc[ii][jj], a2, uj[jj], acc[ii][jj]);
                    FMA_F32X2(acc[ii][jj], b2, vj[jj], acc[ii][jj]);
                }
            }
            if (hasW) {                            // t==1 pixels: essentially never
                unsigned long long wj[8];
#pragma unroll
                for (int jj = 0; jj < 8; jj++)
                    wj[jj] = *reinterpret_cast<unsigned long long*>(
                        &bufR[OFF_W + (j_base + jj) * KIN + kk]);
#pragma unroll
                for (int ii = 0; ii < 4; ii++) {
                    int io = (i_base + ii) * KIN + kk;
                    unsigned long long c2 =
                        *reinterpret_cast<unsigned long long*>(&bufR[OFF_C + io]);
#pragma unroll
                    for (int jj = 0; jj < 8; jj++)
                        FMA_F32X2(acc[ii][jj], c2, wj[jj], acc[ii][jj]);
                }
            }
        }

        // ---- transform next tile into bufW (no barrier between: overlaps FMA)
        int myW2 = 0;
        if (more) myW2 = do_transform(bufW, xr0, xr1, gr);
        hasW = __syncthreads_or(myW2);
    }

    // ---- epilogue: reduce + atomics
    // g_sa: reduce within 16-lane groups (rows fixed per thread)
    {
        float v = saAcc0;
#pragma unroll
        for (int off = 8; off; off >>= 1)
            v += __shfl_xor_sync(0xffffffffu, v, off);
        if (lk == 0)
            atomicAdd(&g_sa[(b * Nc + pr0) * Cc + c], v);
        if (wrp < 9) {                  // q=1 rows 32..49 live in warps 0..8
            float v1 = saAcc1;
#pragma unroll
            for (int off = 8; off; off >>= 1)
                v1 += __shfl_xor_sync(0xffffffffu, v1, off);
            if (lk == 0)
                atomicAdd(&g_sa[(b * Nc + pr1) * Cc + c], v1);
        }
    }
    // g_acc
#pragma unroll
    for (int ii = 0; ii < 4; ii++) {
#pragma unroll
        for (int jj = 0; jj < 8; jj++) {
            unsigned long long a = acc[ii][jj];
            float v = __uint_as_float((unsigned)(a & 0xffffffffu)) +
                      __uint_as_float((unsigned)(a >> 32));
#pragma unroll
            for (int off = 8; off; off >>= 1)
                v += __shfl_xor_sync(0xffffffffu, v, off);
            if (lk == 0) {
                int i = i_base + ii, j = j_base + jj;
                if (i < Nc && j < NG)
                    atomicAdd(&g_acc[(b * Nc + i) * NG + j], v);
            }
        }
    }
}

// ---------------------------------------------------------------------------
// Kernel 3: finalize — grid (Nc, Bc), block 256
// hm = (g_acc - sum_{c masked} g_sa[b,i,c]) / num_kp
// ---------------------------------------------------------------------------
__global__ void finalize_kernel(const float* __restrict__ ps,
                                const float* __restrict__ po,
                                const float* __restrict__ go,
                                float* __restrict__ out) {
    int i = blockIdx.x, b = blockIdx.y;
    int tid = threadIdx.x;

    __shared__ float s_off[NG];
    __shared__ float s_kp[NG];
    __shared__ float s_corr[NG];
    __shared__ float s_score;

    if (tid < NG) { s_off[tid] = 0.0f; s_kp[tid] = 0.0f; s_corr[tid] = 0.0f; }
    if (tid == 0) {
        float sv = ps[b * Nc + i];
        float e = __expf(-fabsf(sv));
        float l = __logf(1.0f + e);
        float r = __fdividef(1.0f, 1.0f + e);
        float sig_neg = (sv >= 0.f) ? e * r : r;
        float sp_neg  = fmaxf(-sv, 0.f) + l;
        s_score = 0.25f * sp_neg * sig_neg * sig_neg;
    }
    __syncthreads();

    if (tid < NG * Cc) {                 // 255 threads: (j, c)
        int j = tid / Cc, c = tid % Cc;
        int m = g_mask[(b * NG + j) * Cc + c];
        atomicAdd(&s_kp[j], (float)m);
        if (m) {
            const float* pp = po + ((size_t)((b * Nc + i) * Cc + c)) * 2;
            const float* gp = go + ((size_t)((b * NG + j) * Cc + c)) * 2;
            float s0 = __fdividef(1.0f, 1.0f + __expf(-pp[0]));
            float s1 = __fdividef(1.0f, 1.0f + __expf(-pp[1]));
            float d0 = s0 - gp[0], d1 = s1 - gp[1];
            atomicAdd(&s_off[j], d0 * d0 + d1 * d1);
        } else {
            atomicAdd(&s_corr[j], g_sa[(b * Nc + i) * Cc + c]);
        }
    }
    __syncthreads();

    if (tid < NG) {
        int j = tid;
        float kp = fmaxf(s_kp[j], 1.0f);
        float hm = (g_acc[(b * Nc + i) * NG + j] - s_corr[j]) / kp;
        out[(b * Nc + i) * NG + j] = 2.0f * hm + s_score + s_off[j] / kp * 0.5f;
    }
}

// ---------------------------------------------------------------------------
extern "C" void kernel_launch(void* const* d_in, const int* in_sizes, int n_in,
                              void* d_out, int out_size) {
    const float* ph = (const float*)d_in[0];
    const float* ps = (const float*)d_in[1];
    const float* po = (const float*)d_in[2];
    const float* gh = (const float*)d_in[3];
    const float* go = (const float*)d_in[4];
    float* out = (float*)d_out;

    cudaFuncSetAttribute(gemm_kernel,
                         cudaFuncAttributeMaxDynamicSharedMemorySize,
                         (int)SMEM_BYTES);

    mask_kernel<<<32, THREADS>>>(gh);
    gemm_kernel<<<dim3(HWc / KCHUNK, Cc, Bc), THREADS, SMEM_BYTES>>>(ph, gh);
    finalize_kernel<<<dim3(Nc, Bc), 256>>>(ps, po, go, out);
}

// round 10
// speedup vs baseline: 1.1493x; 1.1493x over previous
#include <cuda_runtime.h>
#include <cuda_bf16.h>
#include <cstdint>

// Problem constants
constexpr int Bc  = 2;
constexpr int Nc  = 50;
constexpr int NG  = 15;
constexpr int Cc  = 17;
constexpr int HWc = 4096;

constexpr int KCHUNK = 1024;
constexpr int KIN    = 64;
constexpr int NIT    = KCHUNK / KIN;   // 16
constexpr int IPAD   = 64;
constexpr int JPAD   = 16;
constexpr int THREADS = 512;
constexpr int XB     = HWc / KCHUNK;   // 4 k-blocks

// one smem buffer: A,B,C [IPAD][KIN], U,V,W [JPAD][KIN]
constexpr int OFF_A = 0;
constexpr int OFF_B = OFF_A + IPAD * KIN;
constexpr int OFF_C = OFF_B + IPAD * KIN;
constexpr int OFF_U = OFF_C + IPAD * KIN;
constexpr int OFF_V = OFF_U + JPAD * KIN;
constexpr int OFF_W = OFF_V + JPAD * KIN;
constexpr int HALF  = OFF_W + JPAD * KIN;
constexpr size_t SMEM_BYTES = 2 * HALF * sizeof(float);  // 120 KB

// Partial accumulators: each gemm block (x,c,b) owns a disjoint slice.
// No zeroing, no atomics needed.
__device__ __align__(16) float g_accp[Bc * Nc * NG * Cc * XB];
__device__ __align__(16) float g_sap [Bc * Nc * Cc * XB];
__device__ __align__(16) int   g_maskp[Bc * NG * Cc * XB];

#define FMA_F32X2(d, a, b, c) \
    asm("fma.rn.f32x2 %0, %1, %2, %3;" : "=l"(d) : "l"(a), "l"(b), "l"(c))

// ---------------------------------------------------------------------------
// Kernel 1: fused transform + 3-term GEMM + mask partials, f32x2,
// double-buffered KIN=64.  grid (4, Cc, Bc) = 136 blocks, block 512.
// warp w: i rows [4w,4w+4); lanes 0-15 -> j 0..7, 16-31 -> j 8..15
// ---------------------------------------------------------------------------
__global__ __launch_bounds__(THREADS, 1)
void gemm_kernel(const float* __restrict__ ph, const float* __restrict__ gh) {
    extern __shared__ float sm[];

    const int xb = blockIdx.x, c = blockIdx.y, b = blockIdx.z;
    const int k0 = xb * KCHUNK;

    const int tid  = threadIdx.x;
    const int lane = tid & 31;
    const int wrp  = tid >> 5;
    const int lk   = lane & 15;
    const int half = lane >> 4;
    const int i_base = wrp * 4;
    const int j_base = half * 8;

    // zero pad rows [Nc, IPAD) in BOTH buffers once
    for (int idx = tid; idx < (IPAD - Nc) * KIN; idx += THREADS) {
#pragma unroll
        for (int bu = 0; bu < 2; bu++) {
            sm[bu * HALF + OFF_A + Nc * KIN + idx] = 0.f;
            sm[bu * HALF + OFF_B + Nc * KIN + idx] = 0.f;
            sm[bu * HALF + OFF_C + Nc * KIN + idx] = 0.f;
        }
    }

    const float* phb = ph + ((size_t)(b * Nc * Cc + c)) * HWc;
    const float* ghb = gh + ((size_t)(b * NG * Cc + c)) * HWc;

    const int pr0 = tid >> 4;                 // q=0 pred row (0..31)
    const int pc0 = (tid & 15) << 2;
    const int pr1 = (tid + THREADS) >> 4;     // q=1 pred row (32..63)
    const bool q1v = (tid < (Nc * (KIN / 4) - THREADS));  // tid < 288
    const int gj   = tid >> 4;                // gt row
    const bool gv  = (tid < JPAD * (KIN / 4));            // tid < 256

    unsigned long long acc[4][8];
#pragma unroll
    for (int ii = 0; ii < 4; ii++)
#pragma unroll
        for (int jj = 0; jj < 8; jj++) acc[ii][jj] = 0ull;

    float saAcc0 = 0.f, saAcc1 = 0.f;   // per-thread Sum_k A (for g_sap)
    int   gfound = 0;                   // any gt>0 in this thread's slice

    float4 xr0, xr1, gr;

    auto do_transform = [&](float* bw, float4 x0, float4 x1, float4 g) -> int {
        int myW = 0;
        {
            float4 a4, b4o, c4;
            float* xs = &x0.x; float* as = &a4.x; float* bs = &b4o.x; float* cs = &c4.x;
#pragma unroll
            for (int qq = 0; qq < 4; qq++) {
                float x = xs[qq];
                float e = __expf(-fabsf(x));
                float l = __logf(1.0f + e);
                float r = __fdividef(1.0f, 1.0f + e);
                float p   = (x >= 0.f) ? r : e * r;
                float omp = (x >= 0.f) ? e * r : r;
                float sp   = fmaxf(x, 0.f) + l;
                float spmx = fmaxf(-x, 0.f) + l;
                float p2 = p * p;
                as[qq] = sp * p2;
                bs[qq] = -(x * p2);
                cs[qq] = spmx * omp * omp;
            }
            saAcc0 += a4.x + a4.y + a4.z + a4.w;
            int so = pr0 * KIN + pc0;
            *reinterpret_cast<float4*>(&bw[OFF_A + so]) = a4;
            *reinterpret_cast<float4*>(&bw[OFF_B + so]) = b4o;
            *reinterpret_cast<float4*>(&bw[OFF_C + so]) = c4;
        }
        if (q1v) {
            float4 a4, b4o, c4;
            float* xs = &x1.x; float* as = &a4.x; float* bs = &b4o.x; float* cs = &c4.x;
#pragma unroll
            for (int qq = 0; qq < 4; qq++) {
                float x = xs[qq];
                float e = __expf(-fabsf(x));
                float l = __logf(1.0f + e);
                float r = __fdividef(1.0f, 1.0f + e);
                float p   = (x >= 0.f) ? r : e * r;
                float omp = (x >= 0.f) ? e * r : r;
                float sp   = fmaxf(x, 0.f) + l;
                float spmx = fmaxf(-x, 0.f) + l;
                float p2 = p * p;
                as[qq] = sp * p2;
                bs[qq] = -(x * p2);
                cs[qq] = spmx * omp * omp;
            }
            saAcc1 += a4.x + a4.y + a4.z + a4.w;
            int so = pr1 * KIN + pc0;
            *reinterpret_cast<float4*>(&bw[OFF_A + so]) = a4;
            *reinterpret_cast<float4*>(&bw[OFF_B + so]) = b4o;
            *reinterpret_cast<float4*>(&bw[OFF_C + so]) = c4;
        }
        if (gv) {
            float4 u4 = {0,0,0,0}, v4 = {0,0,0,0}, w4 = {0,0,0,0};
            if (gj < NG) {
                float* ts = &g.x; float* us = &u4.x; float* vs = &v4.x; float* wsp = &w4.x;
#pragma unroll
                for (int qq = 0; qq < 4; qq++) {
                    float tt = ts[qq];
                    gfound |= (tt > 0.f);
                    if (tt == 1.0f) { wsp[qq] = 1.0f; myW = 1; }
                    else {
                        float o  = 1.0f - tt;
                        float o2 = o * o;
                        float u  = o2 * o2;
                        us[qq] = u; vs[qq] = tt * u;
                    }
                }
            }
            int so = gj * KIN + pc0;
            *reinterpret_cast<float4*>(&bw[OFF_U + so]) = u4;
            *reinterpret_cast<float4*>(&bw[OFF_V + so]) = v4;
            *reinterpret_cast<float4*>(&bw[OFF_W + so]) = w4;
        }
        return myW;
    };

    auto do_load = [&](int kbase) {
        xr0 = *reinterpret_cast<const float4*>(
            &phb[(size_t)pr0 * Cc * HWc + kbase + pc0]);
        if (q1v)
            xr1 = *reinterpret_cast<const float4*>(
                &phb[(size_t)pr1 * Cc * HWc + kbase + pc0]);
        if (gv && gj < NG)
            gr = *reinterpret_cast<const float4*>(
                &ghb[(size_t)gj * Cc * HWc + kbase + pc0]);
    };

    // ---- prologue: tile 0
    do_load(k0);
    int myW = do_transform(sm, xr0, xr1, gr);
    int hasW = __syncthreads_or(myW);

    for (int t = 0; t < NIT; ++t) {
        float* bufR = sm + (t & 1) * HALF;
        float* bufW = sm + ((t + 1) & 1) * HALF;
        const bool more = (t + 1 < NIT);

        if (more) do_load(k0 + (t + 1) * KIN);

        // ---- FMA on bufR
#pragma unroll
        for (int s = 0; s < KIN / 32; ++s) {
            const int kk = 2 * lk + 32 * s;
            unsigned long long uj[8], vj[8];
#pragma unroll
            for (int jj = 0; jj < 8; jj++) {
                int jo = (j_base + jj) * KIN + kk;
                uj[jj] = *reinterpret_cast<unsigned long long*>(&bufR[OFF_U + jo]);
                vj[jj] = *reinterpret_cast<unsigned long long*>(&bufR[OFF_V + jo]);
            }
#pragma unroll
            for (int ii = 0; ii < 4; ii++) {
                int io = (i_base + ii) * KIN + kk;
                unsigned long long a2 =
                    *reinterpret_cast<unsigned long long*>(&bufR[OFF_A + io]);
                unsigned long long b2 =
                    *reinterpret_cast<unsigned long long*>(&bufR[OFF_B + io]);
#pragma unroll
                for (int jj = 0; jj < 8; jj++) {
                    FMA_F32X2(acc[ii][jj], a2, uj[jj], acc[ii][jj]);
                    FMA_F32X2(acc[ii][jj], b2, vj[jj], acc[ii][jj]);
                }
            }
            if (hasW) {                            // t==1 pixels: essentially never
                unsigned long long wj[8];
#pragma unroll
                for (int jj = 0; jj < 8; jj++)
                    wj[jj] = *reinterpret_cast<unsigned long long*>(
                        &bufR[OFF_W + (j_base + jj) * KIN + kk]);
#pragma unroll
                for (int ii = 0; ii < 4; ii++) {
                    int io = (i_base + ii) * KIN + kk;
                    unsigned long long c2 =
                        *reinterpret_cast<unsigned long long*>(&bufR[OFF_C + io]);
#pragma unroll
                    for (int jj = 0; jj < 8; jj++)
                        FMA_F32X2(acc[ii][jj], c2, wj[jj], acc[ii][jj]);
                }
            }
        }

        int myW2 = 0;
        if (more) myW2 = do_transform(bufW, xr0, xr1, gr);
        hasW = __syncthreads_or(myW2);
    }

    // ---- epilogue: reductions + owned-slice stores (no atomics)
    // mask partial: any gt>0 per (gj) over this k-chunk
    {
        unsigned bal = __ballot_sync(0xffffffffu, gfound);
        int any = (bal >> (16 * half)) & 0xFFFF;
        if (lk == 0 && gj < NG)
            g_maskp[((b * NG + gj) * Cc + c) * XB + xb] = (any != 0);
    }
    // g_sap
    {
        float v = saAcc0;
#pragma unroll
        for (int off = 8; off; off >>= 1)
            v += __shfl_xor_sync(0xffffffffu, v, off);
        if (lk == 0)
            g_sap[((b * Nc + pr0) * Cc + c) * XB + xb] = v;
        if (wrp < 9) {               // q=1 rows 32..49 live in warps 0..8
            float v1 = saAcc1;
#pragma unroll
            for (int off = 8; off; off >>= 1)
                v1 += __shfl_xor_sync(0xffffffffu, v1, off);
            if (lk == 0)
                g_sap[((b * Nc + pr1) * Cc + c) * XB + xb] = v1;
        }
    }
    // g_accp
#pragma unroll
    for (int ii = 0; ii < 4; ii++) {
#pragma unroll
        for (int jj = 0; jj < 8; jj++) {
            unsigned long long a = acc[ii][jj];
            float v = __uint_as_float((unsigned)(a & 0xffffffffu)) +
                      __uint_as_float((unsigned)(a >> 32));
#pragma unroll
            for (int off = 8; off; off >>= 1)
                v += __shfl_xor_sync(0xffffffffu, v, off);
            if (lk == 0) {
                int i = i_base + ii, j = j_base + jj;
                if (i < Nc && j < NG)
                    g_accp[(((b * Nc + i) * NG + j) * Cc + c) * XB + xb] = v;
            }
        }
    }
}

// ---------------------------------------------------------------------------
// Kernel 2: finalize — grid (Nc, Bc), block 256
// Sums partials; hm = (acc - sum_{c masked} sa) / num_kp
// ---------------------------------------------------------------------------
__global__ void finalize_kernel(const float* __restrict__ ps,
                                const float* __restrict__ po,
                                const float* __restrict__ go,
                                float* __restrict__ out) {
    int i = blockIdx.x, b = blockIdx.y;
    int tid = threadIdx.x;

    __shared__ float s_off[NG];
    __shared__ float s_kp[NG];
    __shared__ float s_corr[NG];
    __shared__ float s_hm[NG];
    __shared__ float s_score;

    if (tid < NG) {
        s_off[tid] = 0.0f; s_kp[tid] = 0.0f;
        s_corr[tid] = 0.0f; s_hm[tid] = 0.0f;
    }
    if (tid == 0) {
        float sv = ps[b * Nc + i];
        float e = __expf(-fabsf(sv));
        float l = __logf(1.0f + e);
        float r = __fdividef(1.0f, 1.0f + e);
        float sig_neg = (sv >= 0.f) ? e * r : r;
        float sp_neg  = fmaxf(-sv, 0.f) + l;
        s_score = 0.25f * sp_neg * sig_neg * sig_neg;
    }
    __syncthreads();

    if (tid < NG * Cc) {                 // 255 threads: (j, c)
        int j = tid / Cc, c = tid % Cc;

        int4 mp = *reinterpret_cast<const int4*>(
            &g_maskp[((b * NG + j) * Cc + c) * XB]);
        int m = mp.x | mp.y | mp.z | mp.w;

        float4 ap = *reinterpret_cast<const float4*>(
            &g_accp[(((b * Nc + i) * NG + j) * Cc + c) * XB]);
        atomicAdd(&s_hm[j], ap.x + ap.y + ap.z + ap.w);

        atomicAdd(&s_kp[j], m ? 1.0f : 0.0f);
        if (m) {
            const float* pp = po + ((size_t)((b * Nc + i) * Cc + c)) * 2;
            const float* gp = go + ((size_t)((b * NG + j) * Cc + c)) * 2;
            float s0 = __fdividef(1.0f, 1.0f + __expf(-pp[0]));
            float s1 = __fdividef(1.0f, 1.0f + __expf(-pp[1]));
            float d0 = s0 - gp[0], d1 = s1 - gp[1];
            atomicAdd(&s_off[j], d0 * d0 + d1 * d1);
        } else {
            float4 sp4 = *reinterpret_cast<const float4*>(
                &g_sap[((b * Nc + i) * Cc + c) * XB]);
            atomicAdd(&s_corr[j], sp4.x + sp4.y + sp4.z + sp4.w);
        }
    }
    __syncthreads();

    if (tid < NG) {
        int j = tid;
        float kp = fmaxf(s_kp[j], 1.0f);
        float hm = (s_hm[j] - s_corr[j]) / kp;
        out[(b * Nc + i) * NG + j] = 2.0f * hm + s_score + s_off[j] / kp * 0.5f;
    }
}

// ---------------------------------------------------------------------------
extern "C" void kernel_launch(void* const* d_in, const int* in_sizes, int n_in,
                              void* d_out, int out_size) {
    const float* ph = (const float*)d_in[0];
    const float* ps = (const float*)d_in[1];
    const float* po = (const float*)d_in[2];
    const float* gh = (const float*)d_in[3];
    const float* go = (const float*)d_in[4];
    float* out = (float*)d_out;

    cudaFuncSetAttribute(gemm_kernel,
                         cudaFuncAttributeMaxDynamicSharedMemorySize,
                         (int)SMEM_BYTES);

    gemm_kernel<<<dim3(XB, Cc, Bc), THREADS, SMEM_BYTES>>>(ph, gh);
    finalize_kernel<<<dim3(Nc, Bc), 256>>>(ps, po, go, out);
}

// round 11
// speedup vs baseline: 1.2192x; 1.0608x over previous
#include <cuda_runtime.h>
#include <cuda_bf16.h>
#include <cstdint>

// Problem constants
constexpr int Bc  = 2;
constexpr int Nc  = 50;
constexpr int NG  = 15;
constexpr int Cc  = 17;
constexpr int HWc = 4096;

constexpr int KCHUNK = 1024;
constexpr int KIN    = 64;
constexpr int NIT    = KCHUNK / KIN;   // 16
constexpr int IPAD   = 64;
constexpr int JPAD   = 16;
constexpr int THREADS = 512;
constexpr int XB     = HWc / KCHUNK;   // 4 k-blocks

// one smem buffer: A,B,C [IPAD][KIN], U,V,W [JPAD][KIN]
constexpr int OFF_A = 0;
constexpr int OFF_B = OFF_A + IPAD * KIN;
constexpr int OFF_C = OFF_B + IPAD * KIN;
constexpr int OFF_U = OFF_C + IPAD * KIN;
constexpr int OFF_V = OFF_U + JPAD * KIN;
constexpr int OFF_W = OFF_V + JPAD * KIN;
constexpr int HALF  = OFF_W + JPAD * KIN;
constexpr size_t SMEM_BYTES = 2 * HALF * sizeof(float);  // 120 KB

// Partial accumulators: each gemm block (x,c,b) owns a disjoint slice.
// No zeroing, no atomics needed.
__device__ __align__(16) float g_accp[Bc * Nc * NG * Cc * XB];
__device__ __align__(16) float g_sap [Bc * Nc * Cc * XB];
__device__ __align__(16) int   g_maskp[Bc * NG * Cc * XB];

#define FMA_F32X2(d, a, b, c) \
    asm("fma.rn.f32x2 %0, %1, %2, %3;" : "=l"(d) : "l"(a), "l"(b), "l"(c))

// ---------------------------------------------------------------------------
// Kernel 1: fused transform + 3-term GEMM + mask partials, f32x2,
// double-buffered KIN=64.  grid (4, Cc, Bc) = 136 blocks, block 512.
// warp w: i rows [4w,4w+4); lanes 0-15 -> j 0..7, 16-31 -> j 8..15
// (unchanged from the 39.6us baseline)
// ---------------------------------------------------------------------------
__global__ __launch_bounds__(THREADS, 1)
void gemm_kernel(const float* __restrict__ ph, const float* __restrict__ gh) {
    extern __shared__ float sm[];

    const int xb = blockIdx.x, c = blockIdx.y, b = blockIdx.z;
    const int k0 = xb * KCHUNK;

    const int tid  = threadIdx.x;
    const int lane = tid & 31;
    const int wrp  = tid >> 5;
    const int lk   = lane & 15;
    const int half = lane >> 4;
    const int i_base = wrp * 4;
    const int j_base = half * 8;

    // zero pad rows [Nc, IPAD) in BOTH buffers once
    for (int idx = tid; idx < (IPAD - Nc) * KIN; idx += THREADS) {
#pragma unroll
        for (int bu = 0; bu < 2; bu++) {
            sm[bu * HALF + OFF_A + Nc * KIN + idx] = 0.f;
            sm[bu * HALF + OFF_B + Nc * KIN + idx] = 0.f;
            sm[bu * HALF + OFF_C + Nc * KIN + idx] = 0.f;
        }
    }

    const float* phb = ph + ((size_t)(b * Nc * Cc + c)) * HWc;
    const float* ghb = gh + ((size_t)(b * NG * Cc + c)) * HWc;

    const int pr0 = tid >> 4;                 // q=0 pred row (0..31)
    const int pc0 = (tid & 15) << 2;
    const int pr1 = (tid + THREADS) >> 4;     // q=1 pred row (32..63)
    const bool q1v = (tid < (Nc * (KIN / 4) - THREADS));  // tid < 288
    const int gj   = tid >> 4;                // gt row
    const bool gv  = (tid < JPAD * (KIN / 4));            // tid < 256

    unsigned long long acc[4][8];
#pragma unroll
    for (int ii = 0; ii < 4; ii++)
#pragma unroll
        for (int jj = 0; jj < 8; jj++) acc[ii][jj] = 0ull;

    float saAcc0 = 0.f, saAcc1 = 0.f;   // per-thread Sum_k A (for g_sap)
    int   gfound = 0;                   // any gt>0 in this thread's slice

    float4 xr0, xr1, gr;

    auto do_transform = [&](float* bw, float4 x0, float4 x1, float4 g) -> int {
        int myW = 0;
        {
            float4 a4, b4o, c4;
            float* xs = &x0.x; float* as = &a4.x; float* bs = &b4o.x; float* cs = &c4.x;
#pragma unroll
            for (int qq = 0; qq < 4; qq++) {
                float x = xs[qq];
                float e = __expf(-fabsf(x));
                float l = __logf(1.0f + e);
                float r = __fdividef(1.0f, 1.0f + e);
                float p   = (x >= 0.f) ? r : e * r;
                float omp = (x >= 0.f) ? e * r : r;
                float sp   = fmaxf(x, 0.f) + l;
                float spmx = fmaxf(-x, 0.f) + l;
                float p2 = p * p;
                as[qq] = sp * p2;
                bs[qq] = -(x * p2);
                cs[qq] = spmx * omp * omp;
            }
            saAcc0 += a4.x + a4.y + a4.z + a4.w;
            int so = pr0 * KIN + pc0;
            *reinterpret_cast<float4*>(&bw[OFF_A + so]) = a4;
            *reinterpret_cast<float4*>(&bw[OFF_B + so]) = b4o;
            *reinterpret_cast<float4*>(&bw[OFF_C + so]) = c4;
        }
        if (q1v) {
            float4 a4, b4o, c4;
            float* xs = &x1.x; float* as = &a4.x; float* bs = &b4o.x; float* cs = &c4.x;
#pragma unroll
            for (int qq = 0; qq < 4; qq++) {
                float x = xs[qq];
                float e = __expf(-fabsf(x));
                float l = __logf(1.0f + e);
                float r = __fdividef(1.0f, 1.0f + e);
                float p   = (x >= 0.f) ? r : e * r;
                float omp = (x >= 0.f) ? e * r : r;
                float sp   = fmaxf(x, 0.f) + l;
                float spmx = fmaxf(-x, 0.f) + l;
                float p2 = p * p;
                as[qq] = sp * p2;
                bs[qq] = -(x * p2);
                cs[qq] = spmx * omp * omp;
            }
            saAcc1 += a4.x + a4.y + a4.z + a4.w;
            int so = pr1 * KIN + pc0;
            *reinterpret_cast<float4*>(&bw[OFF_A + so]) = a4;
            *reinterpret_cast<float4*>(&bw[OFF_B + so]) = b4o;
            *reinterpret_cast<float4*>(&bw[OFF_C + so]) = c4;
        }
        if (gv) {
            float4 u4 = {0,0,0,0}, v4 = {0,0,0,0}, w4 = {0,0,0,0};
            if (gj < NG) {
                float* ts = &g.x; float* us = &u4.x; float* vs = &v4.x; float* wsp = &w4.x;
#pragma unroll
                for (int qq = 0; qq < 4; qq++) {
                    float tt = ts[qq];
                    gfound |= (tt > 0.f);
                    if (tt == 1.0f) { wsp[qq] = 1.0f; myW = 1; }
                    else {
                        float o  = 1.0f - tt;
                        float o2 = o * o;
                        float u  = o2 * o2;
                        us[qq] = u; vs[qq] = tt * u;
                    }
                }
            }
            int so = gj * KIN + pc0;
            *reinterpret_cast<float4*>(&bw[OFF_U + so]) = u4;
            *reinterpret_cast<float4*>(&bw[OFF_V + so]) = v4;
            *reinterpret_cast<float4*>(&bw[OFF_W + so]) = w4;
        }
        return myW;
    };

    auto do_load = [&](int kbase) {
        xr0 = *reinterpret_cast<const float4*>(
            &phb[(size_t)pr0 * Cc * HWc + kbase + pc0]);
        if (q1v)
            xr1 = *reinterpret_cast<const float4*>(
                &phb[(size_t)pr1 * Cc * HWc + kbase + pc0]);
        if (gv && gj < NG)
            gr = *reinterpret_cast<const float4*>(
                &ghb[(size_t)gj * Cc * HWc + kbase + pc0]);
    };

    // ---- prologue: tile 0
    do_load(k0);
    int myW = do_transform(sm, xr0, xr1, gr);
    int hasW = __syncthreads_or(myW);

    for (int t = 0; t < NIT; ++t) {
        float* bufR = sm + (t & 1) * HALF;
        float* bufW = sm + ((t + 1) & 1) * HALF;
        const bool more = (t + 1 < NIT);

        if (more) do_load(k0 + (t + 1) * KIN);

        // ---- FMA on bufR
#pragma unroll
        for (int s = 0; s < KIN / 32; ++s) {
            const int kk = 2 * lk + 32 * s;
            unsigned long long uj[8], vj[8];
#pragma unroll
            for (int jj = 0; jj < 8; jj++) {
                int jo = (j_base + jj) * KIN + kk;
                uj[jj] = *reinterpret_cast<unsigned long long*>(&bufR[OFF_U + jo]);
                vj[jj] = *reinterpret_cast<unsigned long long*>(&bufR[OFF_V + jo]);
            }
#pragma unroll
            for (int ii = 0; ii < 4; ii++) {
                int io = (i_base + ii) * KIN + kk;
                unsigned long long a2 =
                    *reinterpret_cast<unsigned long long*>(&bufR[OFF_A + io]);
                unsigned long long b2 =
                    *reinterpret_cast<unsigned long long*>(&bufR[OFF_B + io]);
#pragma unroll
                for (int jj = 0; jj < 8; jj++) {
                    FMA_F32X2(acc[ii][jj], a2, uj[jj], acc[ii][jj]);
                    FMA_F32X2(acc[ii][jj], b2, vj[jj], acc[ii][jj]);
                }
            }
            if (hasW) {                            // t==1 pixels: essentially never
                unsigned long long wj[8];
#pragma unroll
                for (int jj = 0; jj < 8; jj++)
                    wj[jj] = *reinterpret_cast<unsigned long long*>(
                        &bufR[OFF_W + (j_base + jj) * KIN + kk]);
#pragma unroll
                for (int ii = 0; ii < 4; ii++) {
                    int io = (i_base + ii) * KIN + kk;
                    unsigned long long c2 =
                        *reinterpret_cast<unsigned long long*>(&bufR[OFF_C + io]);
#pragma unroll
                    for (int jj = 0; jj < 8; jj++)
                        FMA_F32X2(acc[ii][jj], c2, wj[jj], acc[ii][jj]);
                }
            }
        }

        int myW2 = 0;
        if (more) myW2 = do_transform(bufW, xr0, xr1, gr);
        hasW = __syncthreads_or(myW2);
    }

    // ---- epilogue: reductions + owned-slice stores (no atomics)
    // mask partial: any gt>0 per (gj) over this k-chunk
    {
        unsigned bal = __ballot_sync(0xffffffffu, gfound);
        int any = (bal >> (16 * half)) & 0xFFFF;
        if (lk == 0 && gj < NG)
            g_maskp[((b * NG + gj) * Cc + c) * XB + xb] = (any != 0);
    }
    // g_sap
    {
        float v = saAcc0;
#pragma unroll
        for (int off = 8; off; off >>= 1)
            v += __shfl_xor_sync(0xffffffffu, v, off);
        if (lk == 0)
            g_sap[((b * Nc + pr0) * Cc + c) * XB + xb] = v;
        if (wrp < 9) {               // q=1 rows 32..49 live in warps 0..8
            float v1 = saAcc1;
#pragma unroll
            for (int off = 8; off; off >>= 1)
                v1 += __shfl_xor_sync(0xffffffffu, v1, off);
            if (lk == 0)
                g_sap[((b * Nc + pr1) * Cc + c) * XB + xb] = v1;
        }
    }
    // g_accp
#pragma unroll
    for (int ii = 0; ii < 4; ii++) {
#pragma unroll
        for (int jj = 0; jj < 8; jj++) {
            unsigned long long a = acc[ii][jj];
            float v = __uint_as_float((unsigned)(a & 0xffffffffu)) +
                      __uint_as_float((unsigned)(a >> 32));
#pragma unroll
            for (int off = 8; off; off >>= 1)
                v += __shfl_xor_sync(0xffffffffu, v, off);
            if (lk == 0) {
                int i = i_base + ii, j = j_base + jj;
                if (i < Nc && j < NG)
                    g_accp[(((b * Nc + i) * NG + j) * Cc + c) * XB + xb] = v;
            }
        }
    }
}

// ---------------------------------------------------------------------------
// Kernel 2: finalize v2 — ONE WARP per (j, i, b); grid (NG, Nc, Bc) = 1500.
// lane = channel c (0..16). All loads unconditional + independent (high MLP);
// no smem, no barriers, no atomics — pure shuffle reduction.
// ---------------------------------------------------------------------------
__global__ __launch_bounds__(32, 32)
void finalize_kernel(const float* __restrict__ ps,
                     const float* __restrict__ po,
                     const float* __restrict__ go,
                     float* __restrict__ out) {
    const int j = blockIdx.x, i = blockIdx.y, b = blockIdx.z;
    const int lane = threadIdx.x;
    const bool valid = (lane < Cc);
    const int c = valid ? lane : 0;          // clamp for safe addressing

    // ---- issue ALL loads up-front, independent
    int4   mp  = *reinterpret_cast<const int4*>(
        &g_maskp[((b * NG + j) * Cc + c) * XB]);
    float4 ap  = *reinterpret_cast<const float4*>(
        &g_accp[(((b * Nc + i) * NG + j) * Cc + c) * XB]);
    float4 sp4 = *reinterpret_cast<const float4*>(
        &g_sap[((b * Nc + i) * Cc + c) * XB]);
    float  p0  = __ldg(&po[((size_t)((b * Nc + i) * Cc + c)) * 2 + 0]);
    float  p1  = __ldg(&po[((size_t)((b * Nc + i) * Cc + c)) * 2 + 1]);
    float  g0  = __ldg(&go[((size_t)((b * NG + j) * Cc + c)) * 2 + 0]);
    float  g1  = __ldg(&go[((size_t)((b * NG + j) * Cc + c)) * 2 + 1]);
    float  sv  = __ldg(&ps[b * Nc + i]);     // broadcast-same per warp

    // ---- per-lane values
    int   m   = valid ? ((mp.x | mp.y | mp.z | mp.w) != 0) : 0;
    float hmc = valid ? (ap.x + ap.y + ap.z + ap.w) : 0.f;
    float sac = sp4.x + sp4.y + sp4.z + sp4.w;

    float s0 = __fdividef(1.0f, 1.0f + __expf(-p0));
    float s1 = __fdividef(1.0f, 1.0f + __expf(-p1));
    float d0 = s0 - g0, d1 = s1 - g1;
    float offc = (valid && m) ? (d0 * d0 + d1 * d1) : 0.f;
    float corr = (valid && !m) ? sac : 0.f;
    float kpc  = (float)m;

    // ---- warp reductions (4 values)
#pragma unroll
    for (int off = 16; off; off >>= 1) {
        hmc  += __shfl_xor_sync(0xffffffffu, hmc,  off);
        offc += __shfl_xor_sync(0xffffffffu, offc, off);
        corr += __shfl_xor_sync(0xffffffffu, corr, off);
        kpc  += __shfl_xor_sync(0xffffffffu, kpc,  off);
    }

    if (lane == 0) {
        // score cost: 0.25 * softplus(-s) * (1 - sigmoid(s))^2
        float e = __expf(-fabsf(sv));
        float l = __logf(1.0f + e);
        float r = __fdividef(1.0f, 1.0f + e);
        float sig_neg = (sv >= 0.f) ? e * r : r;
        float sp_neg  = fmaxf(-sv, 0.f) + l;
        float score = 0.25f * sp_neg * sig_neg * sig_neg;

        float kp = fmaxf(kpc, 1.0f);
        float hm = (hmc - corr) / kp;
        out[(b * Nc + i) * NG + j] = 2.0f * hm + score + offc / kp * 0.5f;
    }
}

// ---------------------------------------------------------------------------
extern "C" void kernel_launch(void* const* d_in, const int* in_sizes, int n_in,
                              void* d_out, int out_size) {
    const float* ph = (const float*)d_in[0];
    const float* ps = (const float*)d_in[1];
    const float* po = (const float*)d_in[2];
    const float* gh = (const float*)d_in[3];
    const float* go = (const float*)d_in[4];
    float* out = (float*)d_out;

    cudaFuncSetAttribute(gemm_kernel,
                         cudaFuncAttributeMaxDynamicSharedMemorySize,
                         (int)SMEM_BYTES);

    gemm_kernel<<<dim3(XB, Cc, Bc), THREADS, SMEM_BYTES>>>(ph, gh);
    finalize_kernel<<<dim3(NG, Nc, Bc), 32>>>(ps, po, go, out);
}